// round 5
// baseline (speedup 1.0000x reference)
#include <cuda_runtime.h>
#include <math.h>

#define LS 65536      // layer size (256 x 256 sheet)
#define OS 2048       // out size (8 rows x 256 cols of the sheet)
#define SHEET_W 256
#define INF_RATE 0.1f
#define FILT 5
#define BUSY_ROWS 3328        // m < 3328 (rm <= 12) have nonzero weight rows
#define TASKS (BUSY_ROWS * 8) // 26624 = 256 blocks * 104 tasks
#define TPB_TASKS 104
#define NBLK 256
#define REDUCER 255

// Scratch (no cudaMalloc). Zero-initialized at module load.
__device__ float                 g_dot[BUSY_ROWS];
__device__ double2               g_part[NBLK];
__device__ float                 g_thresh;
__device__ volatile unsigned int g_A[NBLK];   // phase-0 done flags (gen-stamped)
__device__ volatile unsigned int g_B[NBLK];   // partials done flags (gen-stamped)
__device__ volatile unsigned int g_C;         // threshold released (gen counter)

// Single fused kernel, grid 256 x 256. All blocks co-resident (8 warps, tiny
// smem -> >=2 blocks/SM capacity), so flag-spin barriers are safe.
__global__ void __launch_bounds__(256) fused(
    const float* __restrict__ bu,
    const float* __restrict__ r_act,
    const float* __restrict__ r_out,
    const float* __restrict__ x,      // nextlayer_r_out [2048]
    const float* __restrict__ wt,     // weights [65536, 2048]
    float* __restrict__ out)          // [3*65536]: e | ra_thresholded | tanh
{
    const int bid  = blockIdx.x;
    const int tid  = threadIdx.x;
    const int m    = bid * 256 + tid;
    const int lane = tid & 31;
    const int wid  = tid >> 5;

    // Launch generation: g_C advances exactly once per launch, strictly after
    // every block has read it (reducer waits on all B, B set after this read).
    const unsigned int myC = g_C;
    const unsigned int target = myC + 1u;

    // Prefetch elementwise operands (overlaps phase 0)
    const float v_bu = bu[m];
    const float v_ra = r_act[m];
    const float v_ro = r_out[m];

    // ---- Phase 0: dot-product windows, 104 tasks per block, 1 per thread ----
    // task = row*8 + rn. W[m][n]==0.0f exactly outside the connectivity disc,
    // so the fixed aligned 16-float window adds only exact zeros.
    const int task = bid * TPB_TASKS + tid;
    float part = 0.0f;
    if (tid < TPB_TASKS) {
        int row = task >> 3;          // busy row 0..3327
        int rn  = task & 7;
        int rm  = row >> 8;
        int cm  = row & 255;
        if (rn >= rm - FILT && rn <= rm + FILT) {
            int base = (cm - FILT) & ~3;
            if (base < 0) base = 0;
            if (base > SHEET_W - 16) base = SHEET_W - 16;
            int off = rn * SHEET_W + base;
            const float4* w4 = (const float4*)(wt + (size_t)row * OS + off);
            const float4* x4 = (const float4*)(x + off);
            float4 w0 = __ldg(w4 + 0), w1 = __ldg(w4 + 1);
            float4 w2 = __ldg(w4 + 2), w3 = __ldg(w4 + 3);
            float4 x0 = __ldg(x4 + 0), x1 = __ldg(x4 + 1);
            float4 x2 = __ldg(x4 + 2), x3 = __ldg(x4 + 3);
            part = fmaf(w0.x, x0.x, part); part = fmaf(w0.y, x0.y, part);
            part = fmaf(w0.z, x0.z, part); part = fmaf(w0.w, x0.w, part);
            part = fmaf(w1.x, x1.x, part); part = fmaf(w1.y, x1.y, part);
            part = fmaf(w1.z, x1.z, part); part = fmaf(w1.w, x1.w, part);
            part = fmaf(w2.x, x2.x, part); part = fmaf(w2.y, x2.y, part);
            part = fmaf(w2.z, x2.z, part); part = fmaf(w2.w, x2.w, part);
            part = fmaf(w3.x, x3.x, part); part = fmaf(w3.y, x3.y, part);
            part = fmaf(w3.z, x3.z, part); part = fmaf(w3.w, x3.w, part);
        }
    }
    // Reduce the 8 windows of a row (all threads execute: full-mask shuffles)
    part += __shfl_down_sync(0xffffffffu, part, 4, 8);
    part += __shfl_down_sync(0xffffffffu, part, 2, 8);
    part += __shfl_down_sync(0xffffffffu, part, 1, 8);
    if (tid < TPB_TASKS && (tid & 7) == 0) g_dot[task >> 3] = part;

    __threadfence();
    __syncthreads();
    if (tid == 0) g_A[bid] = target;

    // ---- Consumers (blocks 0..12) wait for all phase-0 flags in parallel ----
    float dot = 0.0f;
    if (bid * 256 < BUSY_ROWS) {
        int ok;
        do { ok = (g_A[tid] == target); } while (!__syncthreads_and(ok));
        __threadfence();
        dot = g_dot[m];
    }

    // ---- Elementwise update ----
    float e  = v_ro - dot;
    float ra = v_ra + INF_RATE * (v_bu - e);
    out[m] = e;

    // ---- Block reduction (double, warp shuffles) -> per-block partials ----
    double s = (double)ra;
    double q = (double)ra * (double)ra;
    #pragma unroll
    for (int o = 16; o > 0; o >>= 1) {
        s += __shfl_down_sync(0xffffffffu, s, o);
        q += __shfl_down_sync(0xffffffffu, q, o);
    }
    __shared__ double wsum[8], wsq[8];
    if (lane == 0) { wsum[wid] = s; wsq[wid] = q; }
    __syncthreads();
    if (tid == 0) {
        double bs = 0.0, bq = 0.0;
        #pragma unroll
        for (int i = 0; i < 8; i++) { bs += wsum[i]; bq += wsq[i]; }
        g_part[bid] = make_double2(bs, bq);
        __threadfence();
        g_B[bid] = target;
    }

    // ---- Reducer block aggregates partials; everyone else waits for g_C ----
    if (bid == REDUCER) {
        int ok;
        do { ok = (g_B[tid] == target); } while (!__syncthreads_and(ok));
        __threadfence();
        double2 p = g_part[tid];
        double ps = p.x, pq = p.y;
        #pragma unroll
        for (int o = 16; o > 0; o >>= 1) {
            ps += __shfl_down_sync(0xffffffffu, ps, o);
            pq += __shfl_down_sync(0xffffffffu, pq, o);
        }
        if (lane == 0) { wsum[wid] = ps; wsq[wid] = pq; }
        __syncthreads();
        if (tid == 0) {
            double sum = 0.0, sq = 0.0;
            #pragma unroll
            for (int i = 0; i < 8; i++) { sum += wsum[i]; sq += wsq[i]; }
            double mean = sum / (double)LS;
            double var  = (sq - sum * sum / (double)LS) / (double)(LS - 1);
            if (var < 0.0) var = 0.0;
            g_thresh = (float)(mean + 0.25 * sqrt(var));
            __threadfence();
            g_C = target;   // release
        }
        __syncthreads();
    } else {
        int ok;
        do { ok = (g_C == target); } while (!__syncthreads_and(ok));
        __threadfence();   // acquire
    }

    // ---- Threshold + tanh on register-resident ra ----
    float th = *(volatile float*)&g_thresh;
    float r  = (ra < th) ? -1.0f : ra;
    out[LS + m]     = r;
    out[2 * LS + m] = tanhf(r);
}

extern "C" void kernel_launch(void* const* d_in, const int* in_sizes, int n_in,
                              void* d_out, int out_size)
{
    const float* bu    = (const float*)d_in[0];  // bu_errors [65536]
    const float* r_act = (const float*)d_in[1];  // r_act     [65536]
    const float* r_out = (const float*)d_in[2];  // r_out     [65536]
    const float* x     = (const float*)d_in[3];  // nextlayer_r_out [2048]
    const float* wt    = (const float*)d_in[4];  // weights [65536*2048]
    float* out = (float*)d_out;

    fused<<<NBLK, 256>>>(bu, r_act, r_out, x, wt, out);
}

// round 7
// speedup vs baseline: 1.1530x; 1.1530x over previous
#include <cuda_runtime.h>
#include <math.h>

#define LS 65536      // layer size (256 x 256 sheet)
#define OS 2048       // out size (8 rows x 256 cols of the sheet)
#define SHEET_W 256
#define INF_RATE 0.1f
#define FILT 5
#define BUSY_ROWS 3328        // m < 3328 (rm <= 12) have nonzero weight rows
#define PROD_BLOCKS 104       // 3328 rows * 8 windows / 256 threads-per-block
#define NBLK 256
#define REDUCER 255           // not a producer, not a busy block

// Scratch (no cudaMalloc). Zero-initialized at module load. All counters are
// monotone across launches (epoch-stamped targets) -> replay-deterministic.
__device__ float        g_dot[BUSY_ROWS];
__device__ double2      g_part[NBLK];
__device__ float        g_thresh;
__device__ unsigned int g_count1;   // producer arrivals (+104 per launch)
__device__ unsigned int g_count2;   // partial arrivals  (+256 per launch)
__device__ unsigned int g_epoch;    // launch counter (advanced by reducer)

// ---- acquire/release primitives (no MEMBAR.ALL on the critical path) ----
__device__ __forceinline__ unsigned int ld_acq(const unsigned int* p) {
    unsigned int v;
    asm volatile("ld.acquire.gpu.global.u32 %0, [%1];" : "=r"(v) : "l"(p) : "memory");
    return v;
}
__device__ __forceinline__ unsigned int ld_cg(const unsigned int* p) {
    unsigned int v;
    asm volatile("ld.global.cg.u32 %0, [%1];" : "=r"(v) : "l"(p) : "memory");
    return v;
}
__device__ __forceinline__ void red_rel_add(unsigned int* p, unsigned int v) {
    asm volatile("red.release.gpu.global.add.u32 [%0], %1;" :: "l"(p), "r"(v) : "memory");
}
__device__ __forceinline__ void st_rel(unsigned int* p, unsigned int v) {
    asm volatile("st.release.gpu.global.u32 [%0], %1;" :: "l"(p), "r"(v) : "memory");
}
__device__ __forceinline__ int not_reached(const unsigned int* p, unsigned int target) {
    return (int)(ld_acq(p) - target) < 0;   // wrap-safe
}

// Single fused kernel, grid 256 x 256. All blocks co-resident -> spins are safe.
__global__ void __launch_bounds__(256) fused(
    const float* __restrict__ bu,
    const float* __restrict__ r_act,
    const float* __restrict__ r_out,
    const float* __restrict__ x,      // nextlayer_r_out [2048]
    const float* __restrict__ wt,     // weights [65536, 2048]
    float* __restrict__ out)          // [3*65536]: e | ra_thresholded | tanh
{
    const int bid  = blockIdx.x;
    const int tid  = threadIdx.x;
    const int m    = bid * 256 + tid;
    const int lane = tid & 31;
    const int wid  = tid >> 5;

    __shared__ double wsum[8], wsq[8];
    __shared__ unsigned int s_epoch;

    if (tid == 0) s_epoch = ld_cg(&g_epoch);   // entry read; epoch can only
                                               // advance after ALL blocks pass
                                               // their barrier-2 arrival.

    // Prefetch elementwise operands (overlaps phase 0)
    const float v_bu = bu[m];
    const float v_ra = r_act[m];
    const float v_ro = r_out[m];

    // ---- Phase 0 (blocks 0..103): one (row, rn) window per thread ----
    // task = m = bid*256 + tid covers tasks 0..26623 exactly once (R4 mapping).
    // W[m][n] == 0.0f exactly outside the connectivity disc, so the fixed
    // aligned 16-float window adds only exact zeros.
    if (bid < PROD_BLOCKS) {
        const int task = m;           // 0..26623
        int row = task >> 3;          // busy row 0..3327
        int rn  = task & 7;
        int rm  = row >> 8;
        int cm  = row & 255;
        float part = 0.0f;
        if (rn >= rm - FILT && rn <= rm + FILT) {
            int base = (cm - FILT) & ~3;
            if (base < 0) base = 0;
            if (base > SHEET_W - 16) base = SHEET_W - 16;
            int off = rn * SHEET_W + base;
            const float4* w4 = (const float4*)(wt + (size_t)row * OS + off);
            const float4* x4 = (const float4*)(x + off);
            float4 w0 = __ldg(w4 + 0), w1 = __ldg(w4 + 1);
            float4 w2 = __ldg(w4 + 2), w3 = __ldg(w4 + 3);
            float4 x0 = __ldg(x4 + 0), x1 = __ldg(x4 + 1);
            float4 x2 = __ldg(x4 + 2), x3 = __ldg(x4 + 3);
            part = fmaf(w0.x, x0.x, part); part = fmaf(w0.y, x0.y, part);
            part = fmaf(w0.z, x0.z, part); part = fmaf(w0.w, x0.w, part);
            part = fmaf(w1.x, x1.x, part); part = fmaf(w1.y, x1.y, part);
            part = fmaf(w1.z, x1.z, part); part = fmaf(w1.w, x1.w, part);
            part = fmaf(w2.x, x2.x, part); part = fmaf(w2.y, x2.y, part);
            part = fmaf(w2.z, x2.z, part); part = fmaf(w2.w, x2.w, part);
            part = fmaf(w3.x, x3.x, part); part = fmaf(w3.y, x3.y, part);
            part = fmaf(w3.z, x3.z, part); part = fmaf(w3.w, x3.w, part);
        }
        // Reduce the 8 windows of each row (8 consecutive lanes)
        part += __shfl_down_sync(0xffffffffu, part, 4, 8);
        part += __shfl_down_sync(0xffffffffu, part, 2, 8);
        part += __shfl_down_sync(0xffffffffu, part, 1, 8);
        if ((tid & 7) == 0) g_dot[task >> 3] = part;
        __syncthreads();                            // block's g_dot stores done
        if (tid == 0) red_rel_add(&g_count1, 1u);   // release-arrival
    }
    __syncthreads();   // publishes s_epoch block-wide (and aligns producers)
    const unsigned int E = s_epoch;

    // ---- Consumers (blocks 0..12) wait for the 104 producer arrivals ----
    float dot = 0.0f;
    if (bid < (BUSY_ROWS / 256)) {
        const unsigned int t1 = (E + 1u) * (unsigned)PROD_BLOCKS;
        if (tid == 0) { while (not_reached(&g_count1, t1)) { } }
        __syncthreads();
        dot = g_dot[m];
    }

    // ---- Elementwise update ----
    float e  = v_ro - dot;
    float ra = v_ra + INF_RATE * (v_bu - e);
    out[m] = e;

    // ---- Block reduction (double, warp shuffles) -> per-block partials ----
    double s = (double)ra;
    double q = (double)ra * (double)ra;
    #pragma unroll
    for (int o = 16; o > 0; o >>= 1) {
        s += __shfl_down_sync(0xffffffffu, s, o);
        q += __shfl_down_sync(0xffffffffu, q, o);
    }
    if (lane == 0) { wsum[wid] = s; wsq[wid] = q; }
    __syncthreads();
    if (tid == 0) {
        double bs = 0.0, bq = 0.0;
        #pragma unroll
        for (int i = 0; i < 8; i++) { bs += wsum[i]; bq += wsq[i]; }
        g_part[bid] = make_double2(bs, bq);        // tid0's own store,
        red_rel_add(&g_count2, 1u);                // ordered by this release
    }

    // ---- Fixed reducer (block 255) aggregates; everyone waits on epoch ----
    if (bid == REDUCER) {
        const unsigned int t2 = (E + 1u) * (unsigned)NBLK;
        if (tid == 0) { while (not_reached(&g_count2, t2)) { } }
        __syncthreads();
        double2 p = g_part[tid];
        double ps = p.x, pq = p.y;
        #pragma unroll
        for (int o = 16; o > 0; o >>= 1) {
            ps += __shfl_down_sync(0xffffffffu, ps, o);
            pq += __shfl_down_sync(0xffffffffu, pq, o);
        }
        if (lane == 0) { wsum[wid] = ps; wsq[wid] = pq; }
        __syncthreads();
        if (tid == 0) {
            double sum = 0.0, sq = 0.0;
            #pragma unroll
            for (int i = 0; i < 8; i++) { sum += wsum[i]; sq += wsq[i]; }
            double mean = sum / (double)LS;
            double var  = (sq - sum * sum / (double)LS) / (double)(LS - 1);
            if (var < 0.0) var = 0.0;
            g_thresh = (float)(mean + 0.25 * sqrt(var));
            st_rel(&g_epoch, E + 1u);   // release: publishes g_thresh
        }
        __syncthreads();
    } else {
        if (tid == 0) { while (ld_acq(&g_epoch) == E) { } }
        __syncthreads();   // acquire by tid0 + bar covers whole block
    }

    // ---- Threshold + tanh on register-resident ra ----
    float th = *(volatile float*)&g_thresh;
    float r  = (ra < th) ? -1.0f : ra;
    out[LS + m]     = r;
    out[2 * LS + m] = tanhf(r);
}

extern "C" void kernel_launch(void* const* d_in, const int* in_sizes, int n_in,
                              void* d_out, int out_size)
{
    const float* bu    = (const float*)d_in[0];  // bu_errors [65536]
    const float* r_act = (const float*)d_in[1];  // r_act     [65536]
    const float* r_out = (const float*)d_in[2];  // r_out     [65536]
    const float* x     = (const float*)d_in[3];  // nextlayer_r_out [2048]
    const float* wt    = (const float*)d_in[4];  // weights [65536*2048]
    float* out = (float*)d_out;

    fused<<<NBLK, 256>>>(bu, r_act, r_out, x, wt, out);
}

// round 8
// speedup vs baseline: 1.3113x; 1.1373x over previous
#include <cuda_runtime.h>
#include <math.h>

#define LS 65536      // layer size (256 x 256 sheet)
#define OS 2048       // out size (8 rows x 256 cols of the sheet)
#define SHEET_W 256
#define INF_RATE 0.1f
#define FILT 5
#define BUSY_ROWS 3328        // m < 3328 (rm <= 12) have nonzero weight rows
#define PROD_BLOCKS 104       // each computes 256 window-tasks = 32 busy rows
#define NBLK 256
#define REDUCER 255           // not a producer
#define NB_PER_BLK 243        // (65536 - 3328) / 256 non-busy elements per block

// Scratch (no cudaMalloc). Zero-initialized at module load. Counters are
// monotone across launches (epoch-stamped targets) -> replay-deterministic.
__device__ double2      g_part[NBLK];
__device__ float        g_thresh;
__device__ unsigned int g_count;    // reduce-barrier arrivals (+256 per launch)
__device__ unsigned int g_epoch;    // launch counter (advanced by reducer)

__device__ __forceinline__ unsigned int ld_acq(const unsigned int* p) {
    unsigned int v;
    asm volatile("ld.acquire.gpu.global.u32 %0, [%1];" : "=r"(v) : "l"(p) : "memory");
    return v;
}
__device__ __forceinline__ unsigned int ld_cg(const unsigned int* p) {
    unsigned int v;
    asm volatile("ld.global.cg.u32 %0, [%1];" : "=r"(v) : "l"(p) : "memory");
    return v;
}
__device__ __forceinline__ void red_rel_add(unsigned int* p, unsigned int v) {
    asm volatile("red.release.gpu.global.add.u32 [%0], %1;" :: "l"(p), "r"(v) : "memory");
}
__device__ __forceinline__ void st_rel(unsigned int* p, unsigned int v) {
    asm volatile("st.release.gpu.global.u32 [%0], %1;" :: "l"(p), "r"(v) : "memory");
}
__device__ __forceinline__ int not_reached(const unsigned int* p, unsigned int target) {
    return (int)(ld_acq(p) - target) < 0;   // wrap-safe
}

// Single fused kernel, one grid barrier. All 256 blocks co-resident.
__global__ void __launch_bounds__(256) fused(
    const float* __restrict__ bu,
    const float* __restrict__ r_act,
    const float* __restrict__ r_out,
    const float* __restrict__ x,      // nextlayer_r_out [2048]
    const float* __restrict__ wt,     // weights [65536, 2048]
    float* __restrict__ out)          // [3*65536]: e | ra_thresholded | tanh
{
    const int bid  = blockIdx.x;
    const int tid  = threadIdx.x;
    const int lane = tid & 31;
    const int wid  = tid >> 5;

    __shared__ float  sdot[32];       // dots of this producer block's 32 rows
    __shared__ double wsum[8], wsq[8];
    __shared__ unsigned int s_epoch;

    if (tid == 0) s_epoch = ld_cg(&g_epoch);   // entry read; epoch advances only
                                               // after ALL blocks have arrived.

    // ---- Non-busy elementwise (every block, 243 elements, dot == 0) ----
    const bool has1 = (tid < NB_PER_BLK);
    const int  m1   = BUSY_ROWS + bid * NB_PER_BLK + tid;
    float ra1 = 0.0f;
    if (has1) {
        float e1 = r_out[m1];                   // e = r_out - 0
        ra1 = r_act[m1] + INF_RATE * (bu[m1] - e1);
        out[m1] = e1;
    }

    // ---- Producer blocks: 256 window-tasks -> 32 busy rows, owned locally ----
    // W[m][n] == 0.0f exactly outside the connectivity disc, so the fixed
    // aligned 16-float window adds only exact zeros.
    float ra2 = 0.0f;
    int   row2 = 0;
    const bool isprod = (bid < PROD_BLOCKS);
    if (isprod) {
        const int task = bid * 256 + tid;       // 0..26623
        int row = task >> 3;                    // busy row 0..3327
        int rn  = task & 7;
        int rm  = row >> 8;
        int cm  = row & 255;
        float part = 0.0f;
        if (rn >= rm - FILT && rn <= rm + FILT) {
            int base = (cm - FILT) & ~3;
            if (base < 0) base = 0;
            if (base > SHEET_W - 16) base = SHEET_W - 16;
            int off = rn * SHEET_W + base;
            const float4* w4 = (const float4*)(wt + (size_t)row * OS + off);
            const float4* x4 = (const float4*)(x + off);
            float4 w0 = __ldg(w4 + 0), w1 = __ldg(w4 + 1);
            float4 w2 = __ldg(w4 + 2), w3 = __ldg(w4 + 3);
            float4 x0 = __ldg(x4 + 0), x1 = __ldg(x4 + 1);
            float4 x2 = __ldg(x4 + 2), x3 = __ldg(x4 + 3);
            part = fmaf(w0.x, x0.x, part); part = fmaf(w0.y, x0.y, part);
            part = fmaf(w0.z, x0.z, part); part = fmaf(w0.w, x0.w, part);
            part = fmaf(w1.x, x1.x, part); part = fmaf(w1.y, x1.y, part);
            part = fmaf(w1.z, x1.z, part); part = fmaf(w1.w, x1.w, part);
            part = fmaf(w2.x, x2.x, part); part = fmaf(w2.y, x2.y, part);
            part = fmaf(w2.z, x2.z, part); part = fmaf(w2.w, x2.w, part);
            part = fmaf(w3.x, x3.x, part); part = fmaf(w3.y, x3.y, part);
            part = fmaf(w3.z, x3.z, part); part = fmaf(w3.w, x3.w, part);
        }
        // Reduce 8 windows per row (8-lane segments), leader -> smem
        part += __shfl_down_sync(0xffffffffu, part, 4, 8);
        part += __shfl_down_sync(0xffffffffu, part, 2, 8);
        part += __shfl_down_sync(0xffffffffu, part, 1, 8);
        if ((tid & 7) == 0) sdot[tid >> 3] = part;
        __syncthreads();
        // Warp 0 does the 32 busy rows' elementwise (rows 32*bid .. 32*bid+31)
        if (tid < 32) {
            row2 = bid * 32 + tid;
            float e2 = r_out[row2] - sdot[tid];
            ra2 = r_act[row2] + INF_RATE * (bu[row2] - e2);
            out[row2] = e2;
        }
    }
    const bool has2 = (isprod && tid < 32);

    // ---- Block reduction (double, warp shuffles) -> per-block partial ----
    double s = (double)ra1 + (double)ra2;   // inactive contributions are 0.0f
    double q = (double)ra1 * (double)ra1 + (double)ra2 * (double)ra2;
    #pragma unroll
    for (int o = 16; o > 0; o >>= 1) {
        s += __shfl_down_sync(0xffffffffu, s, o);
        q += __shfl_down_sync(0xffffffffu, q, o);
    }
    if (lane == 0) { wsum[wid] = s; wsq[wid] = q; }
    __syncthreads();                        // also publishes s_epoch
    const unsigned int E = s_epoch;
    if (tid == 0) {
        double bs = 0.0, bq = 0.0;
        #pragma unroll
        for (int i = 0; i < 8; i++) { bs += wsum[i]; bq += wsq[i]; }
        g_part[bid] = make_double2(bs, bq);
        red_rel_add(&g_count, 1u);          // release-arrival orders the store
    }

    // ---- The single grid barrier: reducer aggregates, epoch releases ----
    if (bid == REDUCER) {
        const unsigned int t = (E + 1u) * (unsigned)NBLK;
        if (tid == 0) { while (not_reached(&g_count, t)) { } }
        __syncthreads();
        double2 p = g_part[tid];
        double ps = p.x, pq = p.y;
        #pragma unroll
        for (int o = 16; o > 0; o >>= 1) {
            ps += __shfl_down_sync(0xffffffffu, ps, o);
            pq += __shfl_down_sync(0xffffffffu, pq, o);
        }
        if (lane == 0) { wsum[wid] = ps; wsq[wid] = pq; }
        __syncthreads();
        if (tid == 0) {
            double sum = 0.0, sq = 0.0;
            #pragma unroll
            for (int i = 0; i < 8; i++) { sum += wsum[i]; sq += wsq[i]; }
            double mean = sum / (double)LS;
            double var  = (sq - sum * sum / (double)LS) / (double)(LS - 1);
            if (var < 0.0) var = 0.0;
            g_thresh = (float)(mean + 0.25 * sqrt(var));
            st_rel(&g_epoch, E + 1u);       // release: publishes g_thresh
        }
        __syncthreads();
    } else {
        if (tid == 0) { while (ld_acq(&g_epoch) == E) { } }
        __syncthreads();                    // tid0's acquire + bar covers block
    }

    // ---- Tail: threshold + tanh on register-resident ra ----
    const float th = *(volatile float*)&g_thresh;
    if (has1) {
        float r = (ra1 < th) ? -1.0f : ra1;
        out[LS + m1]     = r;
        out[2 * LS + m1] = tanhf(r);
    }
    if (has2) {
        float r = (ra2 < th) ? -1.0f : ra2;
        out[LS + row2]     = r;
        out[2 * LS + row2] = tanhf(r);
    }
}

extern "C" void kernel_launch(void* const* d_in, const int* in_sizes, int n_in,
                              void* d_out, int out_size)
{
    const float* bu    = (const float*)d_in[0];  // bu_errors [65536]
    const float* r_act = (const float*)d_in[1];  // r_act     [65536]
    const float* r_out = (const float*)d_in[2];  // r_out     [65536]
    const float* x     = (const float*)d_in[3];  // nextlayer_r_out [2048]
    const float* wt    = (const float*)d_in[4];  // weights [65536*2048]
    float* out = (float*)d_out;

    fused<<<NBLK, 256>>>(bu, r_act, r_out, x, wt, out);
}